// round 2
// baseline (speedup 1.0000x reference)
#include <cuda_runtime.h>

#define B_   4
#define S_   2048
#define H_   1024
#define NH_  16
#define DH_  64
#define M_   (B_ * S_)   // 8192 rows

// Scratch (allocation-free): 5 x 32MB fp32
__device__ float g_q[B_ * NH_ * S_ * DH_];
__device__ float g_k[B_ * NH_ * S_ * DH_];
__device__ float g_v[B_ * NH_ * S_ * DH_];
__device__ float g_ctx[M_ * H_];
__device__ float g_h[M_ * H_];

// ---------------------------------------------------------------------------
// 128x128x8 register-blocked SGEMM core: C[m,n] = sum_k A[m,k] * W[n,k]
// 256 threads, each computes an 8x8 micro-tile.
// ---------------------------------------------------------------------------
#define BM 128
#define BN 128
#define BK 8

// QKV projection: z in {0,1,2} selects (Wq,bq,g_q), (Wk,bk,g_k), (Wv,bv,g_v).
// Output written directly in [B, NH, S, DH] layout.
__global__ __launch_bounds__(256) void qkv_gemm(
    const float* __restrict__ X,
    const float* __restrict__ Wq, const float* __restrict__ bq,
    const float* __restrict__ Wk, const float* __restrict__ bk,
    const float* __restrict__ Wv, const float* __restrict__ bv)
{
    const float* W;
    const float* bias;
    float* out;
    if (blockIdx.z == 0)      { W = Wq; bias = bq; out = g_q; }
    else if (blockIdx.z == 1) { W = Wk; bias = bk; out = g_k; }
    else                      { W = Wv; bias = bv; out = g_v; }

    __shared__ float As[BK][BM];
    __shared__ float Bs[BK][BN];

    const int tid = threadIdx.x;
    const int tx = tid & 15;
    const int ty = tid >> 4;
    const int row0 = blockIdx.y * BM;
    const int col0 = blockIdx.x * BN;

    float acc[8][8] = {};

    const int lRow = tid >> 1;          // 0..127
    const int lCol = (tid & 1) * 4;     // 0 or 4
    const float* Aptr = X + (size_t)(row0 + lRow) * H_ + lCol;
    const float* Bptr = W + (size_t)(col0 + lRow) * H_ + lCol;

    for (int k0 = 0; k0 < H_; k0 += BK) {
        float4 a = *(const float4*)(Aptr + k0);
        float4 b = *(const float4*)(Bptr + k0);
        As[lCol + 0][lRow] = a.x; As[lCol + 1][lRow] = a.y;
        As[lCol + 2][lRow] = a.z; As[lCol + 3][lRow] = a.w;
        Bs[lCol + 0][lRow] = b.x; Bs[lCol + 1][lRow] = b.y;
        Bs[lCol + 2][lRow] = b.z; Bs[lCol + 3][lRow] = b.w;
        __syncthreads();
        #pragma unroll
        for (int k = 0; k < BK; k++) {
            float4 fa0 = *(const float4*)(&As[k][ty * 8]);
            float4 fa1 = *(const float4*)(&As[k][ty * 8 + 4]);
            float4 fb0 = *(const float4*)(&Bs[k][tx * 8]);
            float4 fb1 = *(const float4*)(&Bs[k][tx * 8 + 4]);
            float fa[8] = {fa0.x, fa0.y, fa0.z, fa0.w, fa1.x, fa1.y, fa1.z, fa1.w};
            float fb[8] = {fb0.x, fb0.y, fb0.z, fb0.w, fb1.x, fb1.y, fb1.z, fb1.w};
            #pragma unroll
            for (int i = 0; i < 8; i++)
                #pragma unroll
                for (int j = 0; j < 8; j++)
                    acc[i][j] = fmaf(fa[i], fb[j], acc[i][j]);
        }
        __syncthreads();
    }

    // store with head permute: [m, n] -> [b, nh, s, d]
    #pragma unroll
    for (int j = 0; j < 8; j++) {
        const int n = col0 + tx * 8 + j;
        const float bj = bias[n];
        const int nh = n >> 6;      // n / DH
        const int d  = n & 63;      // n % DH
        #pragma unroll
        for (int i = 0; i < 8; i++) {
            const int m = row0 + ty * 8 + i;
            const int b = m >> 11;      // m / S
            const int s = m & 2047;     // m % S
            out[(((size_t)b * NH_ + nh) * S_ + s) * DH_ + d] = acc[i][j] + bj;
        }
    }
}

// Output projection + bias + residual: g_h = g_ctx @ Wo^T + bo + X
__global__ __launch_bounds__(256) void out_gemm(
    const float* __restrict__ X,
    const float* __restrict__ Wo, const float* __restrict__ bo)
{
    __shared__ float As[BK][BM];
    __shared__ float Bs[BK][BN];

    const int tid = threadIdx.x;
    const int tx = tid & 15;
    const int ty = tid >> 4;
    const int row0 = blockIdx.y * BM;
    const int col0 = blockIdx.x * BN;

    float acc[8][8] = {};

    const int lRow = tid >> 1;
    const int lCol = (tid & 1) * 4;
    const float* Aptr = g_ctx + (size_t)(row0 + lRow) * H_ + lCol;
    const float* Bptr = Wo    + (size_t)(col0 + lRow) * H_ + lCol;

    for (int k0 = 0; k0 < H_; k0 += BK) {
        float4 a = *(const float4*)(Aptr + k0);
        float4 b = *(const float4*)(Bptr + k0);
        As[lCol + 0][lRow] = a.x; As[lCol + 1][lRow] = a.y;
        As[lCol + 2][lRow] = a.z; As[lCol + 3][lRow] = a.w;
        Bs[lCol + 0][lRow] = b.x; Bs[lCol + 1][lRow] = b.y;
        Bs[lCol + 2][lRow] = b.z; Bs[lCol + 3][lRow] = b.w;
        __syncthreads();
        #pragma unroll
        for (int k = 0; k < BK; k++) {
            float4 fa0 = *(const float4*)(&As[k][ty * 8]);
            float4 fa1 = *(const float4*)(&As[k][ty * 8 + 4]);
            float4 fb0 = *(const float4*)(&Bs[k][tx * 8]);
            float4 fb1 = *(const float4*)(&Bs[k][tx * 8 + 4]);
            float fa[8] = {fa0.x, fa0.y, fa0.z, fa0.w, fa1.x, fa1.y, fa1.z, fa1.w};
            float fb[8] = {fb0.x, fb0.y, fb0.z, fb0.w, fb1.x, fb1.y, fb1.z, fb1.w};
            #pragma unroll
            for (int i = 0; i < 8; i++)
                #pragma unroll
                for (int j = 0; j < 8; j++)
                    acc[i][j] = fmaf(fa[i], fb[j], acc[i][j]);
        }
        __syncthreads();
    }

    #pragma unroll
    for (int j = 0; j < 8; j++) {
        const int n = col0 + tx * 8 + j;
        const float bj = bo[n];
        #pragma unroll
        for (int i = 0; i < 8; i++) {
            const int m = row0 + ty * 8 + i;
            const size_t idx = (size_t)m * H_ + n;
            g_h[idx] = acc[i][j] + bj + X[idx];
        }
    }
}

// ---------------------------------------------------------------------------
// Flash attention: one block handles 64 query rows for one (b,h).
// Streams 64-wide KV tiles with online softmax. DH = 64.
// ---------------------------------------------------------------------------
#define QT 64
#define KT 64
#define PAD 65   // smem row stride (conflict avoidance)

__global__ __launch_bounds__(256) void flash_attn()
{
    extern __shared__ float smem[];
    float (*Qs)[PAD] = (float(*)[PAD])(smem);
    float (*Ks)[PAD] = (float(*)[PAD])(smem + QT * PAD);
    float (*Vs)[PAD] = (float(*)[PAD])(smem + 2 * QT * PAD);
    float (*Ps)[PAD] = (float(*)[PAD])(smem + 3 * QT * PAD);

    const int bh = blockIdx.y;            // b*NH + nh
    const int q0 = blockIdx.x * QT;
    const float* Q = g_q + (size_t)bh * S_ * DH_;
    const float* K = g_k + (size_t)bh * S_ * DH_;
    const float* V = g_v + (size_t)bh * S_ * DH_;

    const int tid = threadIdx.x;
    const int tx = tid & 15;
    const int ty = tid >> 4;

    // load Q tile (coalesced)
    for (int e = tid; e < QT * DH_; e += 256) {
        const int r = e >> 6, d = e & 63;
        Qs[r][d] = Q[(size_t)(q0 + r) * DH_ + d];
    }

    float m_i[4], l_i[4], o[4][4];
    #pragma unroll
    for (int i = 0; i < 4; i++) {
        m_i[i] = -1e30f;
        l_i[i] = 0.f;
        #pragma unroll
        for (int j = 0; j < 4; j++) o[i][j] = 0.f;
    }

    const float sc = 0.125f;  // 1/sqrt(DH)

    for (int j0 = 0; j0 < S_; j0 += KT) {
        // load K, V tiles
        for (int e = tid; e < KT * DH_; e += 256) {
            const int r = e >> 6, d = e & 63;
            Ks[r][d] = K[(size_t)(j0 + r) * DH_ + d];
            Vs[r][d] = V[(size_t)(j0 + r) * DH_ + d];
        }
        __syncthreads();

        // scores: s[i][j] = Q[4ty+i] . K[4tx+j]
        float s[4][4] = {};
        #pragma unroll 8
        for (int k = 0; k < DH_; k++) {
            float fa[4], fb[4];
            #pragma unroll
            for (int i = 0; i < 4; i++) fa[i] = Qs[4 * ty + i][k];
            #pragma unroll
            for (int j = 0; j < 4; j++) fb[j] = Ks[4 * tx + j][k];
            #pragma unroll
            for (int i = 0; i < 4; i++)
                #pragma unroll
                for (int j = 0; j < 4; j++)
                    s[i][j] = fmaf(fa[i], fb[j], s[i][j]);
        }

        // online softmax per row
        #pragma unroll
        for (int i = 0; i < 4; i++) {
            float mx = -1e30f;
            #pragma unroll
            for (int j = 0; j < 4; j++) {
                s[i][j] *= sc;
                mx = fmaxf(mx, s[i][j]);
            }
            #pragma unroll
            for (int off = 8; off >= 1; off >>= 1)
                mx = fmaxf(mx, __shfl_xor_sync(0xffffffffu, mx, off, 16));
            const float m_new = fmaxf(m_i[i], mx);
            const float alpha = __expf(m_i[i] - m_new);
            m_i[i] = m_new;
            float rs = 0.f;
            #pragma unroll
            for (int j = 0; j < 4; j++) {
                const float p = __expf(s[i][j] - m_new);
                Ps[4 * ty + i][4 * tx + j] = p;
                rs += p;
            }
            #pragma unroll
            for (int off = 8; off >= 1; off >>= 1)
                rs += __shfl_xor_sync(0xffffffffu, rs, off, 16);
            l_i[i] = l_i[i] * alpha + rs;
            #pragma unroll
            for (int j = 0; j < 4; j++) o[i][j] *= alpha;
        }
        __syncthreads();

        // o += P @ V
        #pragma unroll 8
        for (int jj = 0; jj < KT; jj++) {
            float fp[4], fv[4];
            #pragma unroll
            for (int i = 0; i < 4; i++) fp[i] = Ps[4 * ty + i][jj];
            #pragma unroll
            for (int j = 0; j < 4; j++) fv[j] = Vs[jj][4 * tx + j];
            #pragma unroll
            for (int i = 0; i < 4; i++)
                #pragma unroll
                for (int j = 0; j < 4; j++)
                    o[i][j] = fmaf(fp[i], fv[j], o[i][j]);
        }
        __syncthreads();
    }

    // epilogue: write ctx in [B, S, H] layout
    const int b  = bh >> 4;
    const int nh = bh & 15;
    #pragma unroll
    for (int i = 0; i < 4; i++) {
        const int sq = q0 + 4 * ty + i;
        const float inv = 1.0f / l_i[i];
        #pragma unroll
        for (int j = 0; j < 4; j++) {
            g_ctx[((size_t)b * S_ + sq) * H_ + nh * DH_ + 4 * tx + j] = o[i][j] * inv;
        }
    }
}

// ---------------------------------------------------------------------------
// LayerNorm: one block per row of g_h, writes final output.
// ---------------------------------------------------------------------------
__global__ __launch_bounds__(256) void layernorm(
    const float* __restrict__ gamma, const float* __restrict__ beta,
    float* __restrict__ out)
{
    __shared__ float sh1[8];
    __shared__ float sh2[8];

    const int row = blockIdx.x;
    const int tid = threadIdx.x;
    const float4 v = ((const float4*)(g_h + (size_t)row * H_))[tid];

    float sum = v.x + v.y + v.z + v.w;
    float sq  = v.x * v.x + v.y * v.y + v.z * v.z + v.w * v.w;

    #pragma unroll
    for (int off = 16; off >= 1; off >>= 1) {
        sum += __shfl_xor_sync(0xffffffffu, sum, off);
        sq  += __shfl_xor_sync(0xffffffffu, sq,  off);
    }
    const int wid = tid >> 5;
    if ((tid & 31) == 0) { sh1[wid] = sum; sh2[wid] = sq; }
    __syncthreads();
    if (tid < 8) {
        sum = sh1[tid]; sq = sh2[tid];
        #pragma unroll
        for (int off = 4; off >= 1; off >>= 1) {
            sum += __shfl_xor_sync(0xffu, sum, off);
            sq  += __shfl_xor_sync(0xffu, sq,  off);
        }
        if (tid == 0) { sh1[0] = sum; sh2[0] = sq; }
    }
    __syncthreads();

    const float mean = sh1[0] * (1.0f / H_);
    const float var  = sh2[0] * (1.0f / H_) - mean * mean;
    const float rstd = rsqrtf(var + 1e-12f);

    const float4 g = ((const float4*)gamma)[tid];
    const float4 bt = ((const float4*)beta)[tid];
    float4 r;
    r.x = (v.x - mean) * rstd * g.x + bt.x;
    r.y = (v.y - mean) * rstd * g.y + bt.y;
    r.z = (v.z - mean) * rstd * g.z + bt.z;
    r.w = (v.w - mean) * rstd * g.w + bt.w;
    ((float4*)(out + (size_t)row * H_))[tid] = r;
}

// ---------------------------------------------------------------------------
extern "C" void kernel_launch(void* const* d_in, const int* in_sizes, int n_in,
                              void* d_out, int out_size)
{
    const float* X     = (const float*)d_in[0];
    const float* Wq    = (const float*)d_in[1];
    const float* bq    = (const float*)d_in[2];
    const float* Wk    = (const float*)d_in[3];
    const float* bk    = (const float*)d_in[4];
    const float* Wv    = (const float*)d_in[5];
    const float* bv    = (const float*)d_in[6];
    const float* Wo    = (const float*)d_in[7];
    const float* bo    = (const float*)d_in[8];
    const float* gamma = (const float*)d_in[9];
    const float* beta  = (const float*)d_in[10];
    float* out = (float*)d_out;

    const int attn_smem = 4 * QT * PAD * (int)sizeof(float);  // 66560 B
    cudaFuncSetAttribute(flash_attn, cudaFuncAttributeMaxDynamicSharedMemorySize,
                         attn_smem);

    // 1) QKV projections (one launch, z selects matrix)
    qkv_gemm<<<dim3(H_ / BN, M_ / BM, 3), 256>>>(X, Wq, bq, Wk, bk, Wv, bv);

    // 2) flash attention
    flash_attn<<<dim3(S_ / QT, B_ * NH_), 256, attn_smem>>>();

    // 3) output projection + bias + residual
    out_gemm<<<dim3(H_ / BN, M_ / BM), 256>>>(X, Wo, bo);

    // 4) layernorm -> final output
    layernorm<<<M_, 256>>>(gamma, beta, out);
}

// round 3
// speedup vs baseline: 2.8566x; 2.8566x over previous
#include <cuda_runtime.h>

#define B_   4
#define S_   2048
#define H_   1024
#define NH_  16
#define DH_  64
#define M_   (B_ * S_)   // 8192 rows

// Scratch (allocation-free)
__device__ float g_q[B_ * NH_ * S_ * DH_];
__device__ float g_k[B_ * NH_ * S_ * DH_];
__device__ float g_v[B_ * NH_ * S_ * DH_];
__device__ float g_ctx[M_ * H_];
__device__ float g_h[M_ * H_];

// ---------------------------------------------------------------------------
// tf32 helpers
// ---------------------------------------------------------------------------
__device__ __forceinline__ float f2tf(float f) {
    unsigned u;
    asm("cvt.rna.tf32.f32 %0, %1;" : "=r"(u) : "f"(f));
    return __uint_as_float(u);
}

__device__ __forceinline__ void mma_tf32(float c[4], const unsigned a[4],
                                         const unsigned b[2]) {
    asm volatile(
        "mma.sync.aligned.m16n8k8.row.col.f32.tf32.tf32.f32 "
        "{%0,%1,%2,%3}, {%4,%5,%6,%7}, {%8,%9}, {%0,%1,%2,%3};\n"
        : "+f"(c[0]), "+f"(c[1]), "+f"(c[2]), "+f"(c[3])
        : "r"(a[0]), "r"(a[1]), "r"(a[2]), "r"(a[3]), "r"(b[0]), "r"(b[1]));
}

// ---------------------------------------------------------------------------
// tf32 tensor-core GEMM: C[m,n] = A[m,:] . W[n,:]  (both K-major row-major)
// 128x128 tile, BK=16 double buffered. 8 warps, warp tile 64x32 (Mt=4,Nt=4).
// mode 0: qkv (writes g_q/g_k/g_v head-permuted, +bias)
// mode 1: out-proj (writes g_h = C + bias + residual X)
// ---------------------------------------------------------------------------
#define BK   16
#define ASTR 20   // 20 mod 32 -> conflict-free for (8 rows x 4 cols) frag reads

__global__ __launch_bounds__(256, 2) void gemm_tf32(
    const float* __restrict__ A,      // [M_, H_] activations
    const float* __restrict__ X,      // residual (mode 1) or unused
    const float* __restrict__ Wq, const float* __restrict__ bq,
    const float* __restrict__ Wk, const float* __restrict__ bk,
    const float* __restrict__ Wv, const float* __restrict__ bv,
    int mode)
{
    const float* W;
    const float* bias;
    float* out;
    if (mode == 0) {
        if (blockIdx.z == 0)      { W = Wq; bias = bq; out = g_q; }
        else if (blockIdx.z == 1) { W = Wk; bias = bk; out = g_k; }
        else                      { W = Wv; bias = bv; out = g_v; }
    } else {
        W = Wq; bias = bq; out = g_h;   // Wo, bo passed in Wq/bq slots
    }

    __shared__ float As[2][128 * ASTR];
    __shared__ float Bs[2][128 * ASTR];

    const int tid = threadIdx.x;
    const int lane = tid & 31;
    const int wid = tid >> 5;
    const int g = lane >> 2;          // 0..7
    const int t4 = lane & 3;          // 0..3
    const int warp_m = wid & 1;       // 2 x 64 rows
    const int warp_n = wid >> 1;      // 4 x 32 cols

    const int row0 = blockIdx.y * 128;
    const int col0 = blockIdx.x * 128;

    const int ldr = tid >> 1;               // 0..127
    const int ldc = (tid & 1) * 8;          // 0 or 8
    const float* Ag = A + (size_t)(row0 + ldr) * H_ + ldc;
    const float* Bg = W + (size_t)(col0 + ldr) * H_ + ldc;

    float acc[4][4][4];
    #pragma unroll
    for (int i = 0; i < 4; i++)
        #pragma unroll
        for (int j = 0; j < 4; j++)
            #pragma unroll
            for (int c = 0; c < 4; c++) acc[i][j][c] = 0.f;

    // prefetch iter 0
    float4 ra0 = *(const float4*)(Ag);
    float4 ra1 = *(const float4*)(Ag + 4);
    float4 rb0 = *(const float4*)(Bg);
    float4 rb1 = *(const float4*)(Bg + 4);

    const int NIT = H_ / BK;   // 64
    for (int it = 0; it < NIT; it++) {
        const int p = it & 1;
        float* as = As[p];
        float* bs = Bs[p];
        // store (tf32-rounded)
        {
            float4 w0 = make_float4(f2tf(ra0.x), f2tf(ra0.y), f2tf(ra0.z), f2tf(ra0.w));
            float4 w1 = make_float4(f2tf(ra1.x), f2tf(ra1.y), f2tf(ra1.z), f2tf(ra1.w));
            *(float4*)(as + ldr * ASTR + ldc)     = w0;
            *(float4*)(as + ldr * ASTR + ldc + 4) = w1;
            w0 = make_float4(f2tf(rb0.x), f2tf(rb0.y), f2tf(rb0.z), f2tf(rb0.w));
            w1 = make_float4(f2tf(rb1.x), f2tf(rb1.y), f2tf(rb1.z), f2tf(rb1.w));
            *(float4*)(bs + ldr * ASTR + ldc)     = w0;
            *(float4*)(bs + ldr * ASTR + ldc + 4) = w1;
        }
        __syncthreads();
        if (it + 1 < NIT) {
            const int k0 = (it + 1) * BK;
            ra0 = *(const float4*)(Ag + k0);
            ra1 = *(const float4*)(Ag + k0 + 4);
            rb0 = *(const float4*)(Bg + k0);
            rb1 = *(const float4*)(Bg + k0 + 4);
        }
        const unsigned* asu = (const unsigned*)as;
        const unsigned* bsu = (const unsigned*)bs;
        #pragma unroll
        for (int kk = 0; kk < 2; kk++) {
            const int k0 = kk * 8;
            unsigned af[4][4], bf[4][2];
            #pragma unroll
            for (int mt = 0; mt < 4; mt++) {
                const int r = warp_m * 64 + mt * 16 + g;
                af[mt][0] = asu[r * ASTR + k0 + t4];
                af[mt][1] = asu[(r + 8) * ASTR + k0 + t4];
                af[mt][2] = asu[r * ASTR + k0 + t4 + 4];
                af[mt][3] = asu[(r + 8) * ASTR + k0 + t4 + 4];
            }
            #pragma unroll
            for (int nt = 0; nt < 4; nt++) {
                const int n = warp_n * 32 + nt * 8 + g;
                bf[nt][0] = bsu[n * ASTR + k0 + t4];
                bf[nt][1] = bsu[n * ASTR + k0 + t4 + 4];
            }
            #pragma unroll
            for (int mt = 0; mt < 4; mt++)
                #pragma unroll
                for (int nt = 0; nt < 4; nt++)
                    mma_tf32(acc[mt][nt], af[mt], bf[nt]);
        }
        __syncthreads();
    }

    // epilogue
    #pragma unroll
    for (int mt = 0; mt < 4; mt++) {
        const int rg = row0 + warp_m * 64 + mt * 16 + g;
        #pragma unroll
        for (int nt = 0; nt < 4; nt++) {
            const int n = col0 + warp_n * 32 + nt * 8 + 2 * t4;
            const float b0 = bias[n], b1 = bias[n + 1];
            if (mode == 0) {
                const int nh = n >> 6, d = n & 63;
                #pragma unroll
                for (int h = 0; h < 2; h++) {
                    const int m = rg + h * 8;
                    const int bb = m >> 11, s = m & 2047;
                    float2 v = make_float2(acc[mt][nt][2 * h] + b0,
                                           acc[mt][nt][2 * h + 1] + b1);
                    *(float2*)&out[(((size_t)bb * NH_ + nh) * S_ + s) * DH_ + d] = v;
                }
            } else {
                #pragma unroll
                for (int h = 0; h < 2; h++) {
                    const int m = rg + h * 8;
                    const size_t idx = (size_t)m * H_ + n;
                    float2 r = *(const float2*)&X[idx];
                    float2 v = make_float2(acc[mt][nt][2 * h] + b0 + r.x,
                                           acc[mt][nt][2 * h + 1] + b1 + r.y);
                    *(float2*)&out[idx] = v;
                }
            }
        }
    }
}

// ---------------------------------------------------------------------------
// Flash attention, tf32 tensor cores. 4 warps, 64 q-rows per block.
// Q held in registers as A-fragments; Q smem buffer reused for P.
// ---------------------------------------------------------------------------
#define QSTR 68   // 4 mod 32: conflict-free for (8 rows x 4 cols) pattern
#define VSTR 72   // 8 mod 32: conflict-free for (4 rows x 8 cols) pattern

__global__ __launch_bounds__(128) void flash_attn_tf32()
{
    extern __shared__ float sm[];
    float* QPs = sm;                     // [64][QSTR]  Q, then P
    float* Ks  = sm + 64 * QSTR;         // [64][QSTR]
    float* Vs  = sm + 2 * 64 * QSTR;     // [64][VSTR]
    unsigned* QPu = (unsigned*)QPs;
    unsigned* Ku  = (unsigned*)Ks;
    unsigned* Vu  = (unsigned*)Vs;

    const int bh = blockIdx.y;
    const int q0 = blockIdx.x * 64;
    const float* Q = g_q + (size_t)bh * S_ * DH_;
    const float* K = g_k + (size_t)bh * S_ * DH_;
    const float* V = g_v + (size_t)bh * S_ * DH_;

    const int tid = threadIdx.x;
    const int lane = tid & 31;
    const int wid = tid >> 5;
    const int g = lane >> 2;
    const int t4 = lane & 3;
    const int qr = wid * 16;             // warp's 16 q rows

    // load Q tile (tf32-rounded), extract A fragments to registers
    for (int e = tid; e < 1024; e += 128) {
        const int r = e >> 4, c4 = (e & 15) * 4;
        float4 v = *(const float4*)(Q + (size_t)(q0 + r) * DH_ + c4);
        QPs[r * QSTR + c4 + 0] = f2tf(v.x);
        QPs[r * QSTR + c4 + 1] = f2tf(v.y);
        QPs[r * QSTR + c4 + 2] = f2tf(v.z);
        QPs[r * QSTR + c4 + 3] = f2tf(v.w);
    }
    __syncthreads();

    unsigned qa[8][4];
    #pragma unroll
    for (int kk = 0; kk < 8; kk++) {
        const int r = qr + g;
        qa[kk][0] = QPu[r * QSTR + kk * 8 + t4];
        qa[kk][1] = QPu[(r + 8) * QSTR + kk * 8 + t4];
        qa[kk][2] = QPu[r * QSTR + kk * 8 + t4 + 4];
        qa[kk][3] = QPu[(r + 8) * QSTR + kk * 8 + t4 + 4];
    }

    float m_i[2] = {-1e30f, -1e30f};
    float l_i[2] = {0.f, 0.f};
    float oc[8][4];
    #pragma unroll
    for (int n = 0; n < 8; n++)
        #pragma unroll
        for (int c = 0; c < 4; c++) oc[n][c] = 0.f;

    for (int j0 = 0; j0 < S_; j0 += 64) {
        // load K, V (tf32-rounded) -- also serves as barrier before P writes
        for (int e = tid; e < 1024; e += 128) {
            const int r = e >> 4, c4 = (e & 15) * 4;
            float4 kv = *(const float4*)(K + (size_t)(j0 + r) * DH_ + c4);
            float4 vv = *(const float4*)(V + (size_t)(j0 + r) * DH_ + c4);
            Ks[r * QSTR + c4 + 0] = f2tf(kv.x);
            Ks[r * QSTR + c4 + 1] = f2tf(kv.y);
            Ks[r * QSTR + c4 + 2] = f2tf(kv.z);
            Ks[r * QSTR + c4 + 3] = f2tf(kv.w);
            Vs[r * VSTR + c4 + 0] = f2tf(vv.x);
            Vs[r * VSTR + c4 + 1] = f2tf(vv.y);
            Vs[r * VSTR + c4 + 2] = f2tf(vv.z);
            Vs[r * VSTR + c4 + 3] = f2tf(vv.w);
        }
        __syncthreads();

        // scores = Q . K^T  (per warp: 16 q rows x 64 keys)
        float sc[8][4];
        #pragma unroll
        for (int nt = 0; nt < 8; nt++)
            #pragma unroll
            for (int c = 0; c < 4; c++) sc[nt][c] = 0.f;
        #pragma unroll
        for (int nt = 0; nt < 8; nt++) {
            #pragma unroll
            for (int kk = 0; kk < 8; kk++) {
                unsigned bf[2];
                bf[0] = Ku[(nt * 8 + g) * QSTR + kk * 8 + t4];
                bf[1] = Ku[(nt * 8 + g) * QSTR + kk * 8 + t4 + 4];
                mma_tf32(sc[nt], qa[kk], bf);
            }
        }

        // online softmax (rows g and g+8)
        #pragma unroll
        for (int h = 0; h < 2; h++) {
            const int i0 = h * 2;
            float mx = -1e30f;
            #pragma unroll
            for (int nt = 0; nt < 8; nt++) {
                sc[nt][i0]     *= 0.125f;
                sc[nt][i0 + 1] *= 0.125f;
                mx = fmaxf(mx, fmaxf(sc[nt][i0], sc[nt][i0 + 1]));
            }
            mx = fmaxf(mx, __shfl_xor_sync(0xffffffffu, mx, 1));
            mx = fmaxf(mx, __shfl_xor_sync(0xffffffffu, mx, 2));
            const float m_new = fmaxf(m_i[h], mx);
            const float alpha = __expf(m_i[h] - m_new);
            m_i[h] = m_new;
            float rs = 0.f;
            const int prow = qr + g + h * 8;
            #pragma unroll
            for (int nt = 0; nt < 8; nt++) {
                float p0 = __expf(sc[nt][i0] - m_new);
                float p1 = __expf(sc[nt][i0 + 1] - m_new);
                rs += p0 + p1;
                QPs[prow * QSTR + nt * 8 + 2 * t4]     = f2tf(p0);
                QPs[prow * QSTR + nt * 8 + 2 * t4 + 1] = f2tf(p1);
            }
            rs += __shfl_xor_sync(0xffffffffu, rs, 1);
            rs += __shfl_xor_sync(0xffffffffu, rs, 2);
            l_i[h] = l_i[h] * alpha + rs;
            #pragma unroll
            for (int nt = 0; nt < 8; nt++) {
                oc[nt][i0]     *= alpha;
                oc[nt][i0 + 1] *= alpha;
            }
        }
        __syncwarp();

        // O += P . V   (per warp: 16 q rows x 64 d)
        #pragma unroll
        for (int kk = 0; kk < 8; kk++) {
            unsigned pa[4];
            const int r = qr + g;
            pa[0] = QPu[r * QSTR + kk * 8 + t4];
            pa[1] = QPu[(r + 8) * QSTR + kk * 8 + t4];
            pa[2] = QPu[r * QSTR + kk * 8 + t4 + 4];
            pa[3] = QPu[(r + 8) * QSTR + kk * 8 + t4 + 4];
            #pragma unroll
            for (int nt = 0; nt < 8; nt++) {
                unsigned bf[2];
                bf[0] = Vu[(kk * 8 + t4) * VSTR + nt * 8 + g];
                bf[1] = Vu[(kk * 8 + t4 + 4) * VSTR + nt * 8 + g];
                mma_tf32(oc[nt], pa, bf);
            }
        }
        __syncthreads();
    }

    // epilogue: write ctx in [B, S, H] layout
    const int bb = bh >> 4;
    const int nh = bh & 15;
    const float inv0 = 1.0f / l_i[0];
    const float inv1 = 1.0f / l_i[1];
    #pragma unroll
    for (int nt = 0; nt < 8; nt++) {
        const int d = nt * 8 + 2 * t4;
        const int s0 = q0 + qr + g;
        float2 v0 = make_float2(oc[nt][0] * inv0, oc[nt][1] * inv0);
        float2 v1 = make_float2(oc[nt][2] * inv1, oc[nt][3] * inv1);
        *(float2*)&g_ctx[((size_t)bb * S_ + s0) * H_ + nh * DH_ + d] = v0;
        *(float2*)&g_ctx[((size_t)bb * S_ + s0 + 8) * H_ + nh * DH_ + d] = v1;
    }
}

// ---------------------------------------------------------------------------
// LayerNorm (unchanged)
// ---------------------------------------------------------------------------
__global__ __launch_bounds__(256) void layernorm(
    const float* __restrict__ gamma, const float* __restrict__ beta,
    float* __restrict__ out)
{
    __shared__ float sh1[8];
    __shared__ float sh2[8];

    const int row = blockIdx.x;
    const int tid = threadIdx.x;
    const float4 v = ((const float4*)(g_h + (size_t)row * H_))[tid];

    float sum = v.x + v.y + v.z + v.w;
    float sq  = v.x * v.x + v.y * v.y + v.z * v.z + v.w * v.w;

    #pragma unroll
    for (int off = 16; off >= 1; off >>= 1) {
        sum += __shfl_xor_sync(0xffffffffu, sum, off);
        sq  += __shfl_xor_sync(0xffffffffu, sq,  off);
    }
    const int wid = tid >> 5;
    if ((tid & 31) == 0) { sh1[wid] = sum; sh2[wid] = sq; }
    __syncthreads();
    if (tid < 8) {
        sum = sh1[tid]; sq = sh2[tid];
        #pragma unroll
        for (int off = 4; off >= 1; off >>= 1) {
            sum += __shfl_xor_sync(0xffu, sum, off);
            sq  += __shfl_xor_sync(0xffu, sq,  off);
        }
        if (tid == 0) { sh1[0] = sum; sh2[0] = sq; }
    }
    __syncthreads();

    const float mean = sh1[0] * (1.0f / H_);
    const float var  = sh2[0] * (1.0f / H_) - mean * mean;
    const float rstd = rsqrtf(var + 1e-12f);

    const float4 gv = ((const float4*)gamma)[tid];
    const float4 bt = ((const float4*)beta)[tid];
    float4 r;
    r.x = (v.x - mean) * rstd * gv.x + bt.x;
    r.y = (v.y - mean) * rstd * gv.y + bt.y;
    r.z = (v.z - mean) * rstd * gv.z + bt.z;
    r.w = (v.w - mean) * rstd * gv.w + bt.w;
    ((float4*)(out + (size_t)row * H_))[tid] = r;
}

// ---------------------------------------------------------------------------
extern "C" void kernel_launch(void* const* d_in, const int* in_sizes, int n_in,
                              void* d_out, int out_size)
{
    const float* X     = (const float*)d_in[0];
    const float* Wq    = (const float*)d_in[1];
    const float* bq    = (const float*)d_in[2];
    const float* Wk    = (const float*)d_in[3];
    const float* bk    = (const float*)d_in[4];
    const float* Wv    = (const float*)d_in[5];
    const float* bv    = (const float*)d_in[6];
    const float* Wo    = (const float*)d_in[7];
    const float* bo    = (const float*)d_in[8];
    const float* gamma = (const float*)d_in[9];
    const float* beta  = (const float*)d_in[10];
    float* out = (float*)d_out;

    const int attn_smem = (2 * 64 * QSTR + 64 * VSTR) * (int)sizeof(float); // 53248
    cudaFuncSetAttribute(flash_attn_tf32,
                         cudaFuncAttributeMaxDynamicSharedMemorySize, attn_smem);

    float* g_ctx_ptr = nullptr;
    cudaGetSymbolAddress((void**)&g_ctx_ptr, g_ctx);

    // 1) QKV projections
    gemm_tf32<<<dim3(H_ / 128, M_ / 128, 3), 256>>>(X, nullptr,
                                                    Wq, bq, Wk, bk, Wv, bv, 0);
    // 2) flash attention
    flash_attn_tf32<<<dim3(S_ / 64, B_ * NH_), 128, attn_smem>>>();

    // 3) output projection + bias + residual
    gemm_tf32<<<dim3(H_ / 128, M_ / 128, 1), 256>>>(g_ctx_ptr, X,
                                                    Wo, bo, nullptr, nullptr,
                                                    nullptr, nullptr, 1);
    // 4) layernorm
    layernorm<<<M_, 256>>>(gamma, beta, out);
}

// round 4
// speedup vs baseline: 5.8670x; 2.0539x over previous
#include <cuda_runtime.h>
#include <cuda_bf16.h>

#define B_   4
#define S_   2048
#define H_   1024
#define NH_  16
#define DH_  64
#define M_   (B_ * S_)   // 8192

// -------------------- scratch (allocation-free) ----------------------------
__device__ __nv_bfloat16 g_xb[M_ * H_];
__device__ __nv_bfloat16 g_wq[H_ * H_];
__device__ __nv_bfloat16 g_wk[H_ * H_];
__device__ __nv_bfloat16 g_wv[H_ * H_];
__device__ __nv_bfloat16 g_wo[H_ * H_];
__device__ __nv_bfloat16 g_q[B_ * NH_ * S_ * DH_];
__device__ __nv_bfloat16 g_k[B_ * NH_ * S_ * DH_];
__device__ __nv_bfloat16 g_v[B_ * NH_ * S_ * DH_];
__device__ __nv_bfloat16 g_ctx[M_ * H_];
__device__ float         g_h[M_ * H_];

// -------------------- helpers ----------------------------------------------
__device__ __forceinline__ void mma_bf16(float c[4], const unsigned a[4],
                                         const unsigned b[2]) {
    asm volatile(
        "mma.sync.aligned.m16n8k16.row.col.f32.bf16.bf16.f32 "
        "{%0,%1,%2,%3}, {%4,%5,%6,%7}, {%8,%9}, {%0,%1,%2,%3};\n"
        : "+f"(c[0]), "+f"(c[1]), "+f"(c[2]), "+f"(c[3])
        : "r"(a[0]), "r"(a[1]), "r"(a[2]), "r"(a[3]), "r"(b[0]), "r"(b[1]));
}

__device__ __forceinline__ void cp16(unsigned dst, const void* src) {
    asm volatile("cp.async.cg.shared.global [%0], [%1], 16;\n" ::"r"(dst), "l"(src));
}
__device__ __forceinline__ void cp_commit() {
    asm volatile("cp.async.commit_group;\n");
}
template <int N> __device__ __forceinline__ void cp_wait() {
    asm volatile("cp.async.wait_group %0;\n" ::"n"(N));
}

__device__ __forceinline__ unsigned pack_bf16(float lo, float hi) {
    __nv_bfloat162 p = __float22bfloat162_rn(make_float2(lo, hi));
    return *(unsigned*)&p;
}

// -------------------- fp32 -> bf16 conversion pre-pass ----------------------
__global__ __launch_bounds__(256) void convert_bf16(
    const float* __restrict__ X,
    const float* __restrict__ Wq, const float* __restrict__ Wk,
    const float* __restrict__ Wv, const float* __restrict__ Wo)
{
    const size_t i = ((size_t)blockIdx.x * 256 + threadIdx.x) * 4;
    const float* src;
    __nv_bfloat16* dst;
    size_t off;
    if (i < (size_t)M_ * H_) {
        src = X; dst = g_xb; off = i;
    } else {
        size_t w = i - (size_t)M_ * H_;
        int which = (int)(w >> 20);
        off = w & ((1u << 20) - 1);
        if (which == 0)      { src = Wq; dst = g_wq; }
        else if (which == 1) { src = Wk; dst = g_wk; }
        else if (which == 2) { src = Wv; dst = g_wv; }
        else                 { src = Wo; dst = g_wo; }
    }
    float4 v = *(const float4*)(src + off);
    *(__nv_bfloat162*)(dst + off)     = __float22bfloat162_rn(make_float2(v.x, v.y));
    *(__nv_bfloat162*)(dst + off + 2) = __float22bfloat162_rn(make_float2(v.z, v.w));
}

// ---------------------------------------------------------------------------
// bf16 tensor-core GEMM: C[m,n] = A[m,:] . W[n,:]
// 128x128 tile, BK=32, 4-stage cp.async pipeline. 8 warps, warp tile 64x32.
// mode 0: qkv (z selects W/bias; writes g_q/g_k/g_v bf16, head-permuted, +bias)
// mode 1: out-proj (writes g_h fp32 = C + bias + residual X)
// ---------------------------------------------------------------------------
#define STR  20          // words per smem row (20 mod 32 -> conflict-free frags)
#define STGW (128 * STR) // words per stage per matrix = 2560
#define STG  4

__global__ __launch_bounds__(256, 2) void gemm_bf16(
    const __nv_bfloat16* __restrict__ A,
    const __nv_bfloat16* __restrict__ W0,
    const __nv_bfloat16* __restrict__ W1,
    const __nv_bfloat16* __restrict__ W2,
    const float* __restrict__ b0p,
    const float* __restrict__ b1p,
    const float* __restrict__ b2p,
    const float* __restrict__ Xres,
    int mode)
{
    const __nv_bfloat16* W;
    const float* bias;
    __nv_bfloat16* outb = nullptr;
    if (mode == 0) {
        if (blockIdx.z == 0)      { W = W0; bias = b0p; outb = g_q; }
        else if (blockIdx.z == 1) { W = W1; bias = b1p; outb = g_k; }
        else                      { W = W2; bias = b2p; outb = g_v; }
    } else {
        W = W0; bias = b0p;
    }

    extern __shared__ unsigned smw[];
    unsigned* As = smw;
    unsigned* Bs = smw + STG * STGW;
    const unsigned sA = (unsigned)__cvta_generic_to_shared(As);
    const unsigned sB = (unsigned)__cvta_generic_to_shared(Bs);

    const int tid = threadIdx.x;
    const int lane = tid & 31;
    const int wid = tid >> 5;
    const int g = lane >> 2;
    const int t4 = lane & 3;
    const int warp_m = wid & 1;
    const int warp_n = wid >> 1;

    const int row0 = blockIdx.y * 128;
    const int col0 = blockIdx.x * 128;

    const int ldr = tid >> 1;      // 0..127
    const int hh = tid & 1;        // half of the 32-wide k-slab

    const __nv_bfloat16* Ag = A + (size_t)(row0 + ldr) * H_ + hh * 16;
    const __nv_bfloat16* Bg = W + (size_t)(col0 + ldr) * H_ + hh * 16;
    const unsigned dOffA = sA + (unsigned)(ldr * STR + hh * 8) * 4;
    const unsigned dOffB = sB + (unsigned)(ldr * STR + hh * 8) * 4;

    float acc[4][4][4];
    #pragma unroll
    for (int i = 0; i < 4; i++)
        #pragma unroll
        for (int j = 0; j < 4; j++)
            #pragma unroll
            for (int c = 0; c < 4; c++) acc[i][j][c] = 0.f;

    const int NIT = H_ / 32;   // 32

    // pipeline prologue: stages 0..2
    #pragma unroll
    for (int s = 0; s < STG - 1; s++) {
        const int k0 = s * 32;
        const unsigned so = (unsigned)(s * STGW) * 4;
        cp16(dOffA + so,      Ag + k0);
        cp16(dOffA + so + 16, Ag + k0 + 8);
        cp16(dOffB + so,      Bg + k0);
        cp16(dOffB + so + 16, Bg + k0 + 8);
        cp_commit();
    }

    for (int it = 0; it < NIT; it++) {
        cp_wait<STG - 2>();
        __syncthreads();

        if (it + STG - 1 < NIT) {
            const int s = (it + STG - 1) & (STG - 1);
            const int k0 = (it + STG - 1) * 32;
            const unsigned so = (unsigned)(s * STGW) * 4;
            cp16(dOffA + so,      Ag + k0);
            cp16(dOffA + so + 16, Ag + k0 + 8);
            cp16(dOffB + so,      Bg + k0);
            cp16(dOffB + so + 16, Bg + k0 + 8);
        }
        cp_commit();

        const unsigned* as = As + (it & (STG - 1)) * STGW;
        const unsigned* bs = Bs + (it & (STG - 1)) * STGW;
        #pragma unroll
        for (int kk = 0; kk < 2; kk++) {
            const int kw = kk * 8;
            unsigned af[4][4], bf[4][2];
            #pragma unroll
            for (int mt = 0; mt < 4; mt++) {
                const int r = warp_m * 64 + mt * 16 + g;
                af[mt][0] = as[r * STR + kw + t4];
                af[mt][1] = as[(r + 8) * STR + kw + t4];
                af[mt][2] = as[r * STR + kw + t4 + 4];
                af[mt][3] = as[(r + 8) * STR + kw + t4 + 4];
            }
            #pragma unroll
            for (int nt = 0; nt < 4; nt++) {
                const int n = warp_n * 32 + nt * 8 + g;
                bf[nt][0] = bs[n * STR + kw + t4];
                bf[nt][1] = bs[n * STR + kw + t4 + 4];
            }
            #pragma unroll
            for (int mt = 0; mt < 4; mt++)
                #pragma unroll
                for (int nt = 0; nt < 4; nt++)
                    mma_bf16(acc[mt][nt], af[mt], bf[nt]);
        }
    }

    // epilogue
    #pragma unroll
    for (int mt = 0; mt < 4; mt++) {
        const int rg = row0 + warp_m * 64 + mt * 16 + g;
        #pragma unroll
        for (int nt = 0; nt < 4; nt++) {
            const int n = col0 + warp_n * 32 + nt * 8 + 2 * t4;
            const float b0 = bias[n], b1 = bias[n + 1];
            if (mode == 0) {
                const int nh = n >> 6, d = n & 63;
                #pragma unroll
                for (int h = 0; h < 2; h++) {
                    const int m = rg + h * 8;
                    const int bb = m >> 11, s = m & 2047;
                    __nv_bfloat162 v = __float22bfloat162_rn(
                        make_float2(acc[mt][nt][2 * h] + b0,
                                    acc[mt][nt][2 * h + 1] + b1));
                    *(__nv_bfloat162*)&outb[(((size_t)bb * NH_ + nh) * S_ + s) * DH_ + d] = v;
                }
            } else {
                #pragma unroll
                for (int h = 0; h < 2; h++) {
                    const int m = rg + h * 8;
                    const size_t idx = (size_t)m * H_ + n;
                    float2 r = *(const float2*)&Xres[idx];
                    float2 v = make_float2(acc[mt][nt][2 * h] + b0 + r.x,
                                           acc[mt][nt][2 * h + 1] + b1 + r.y);
                    *(float2*)&g_h[idx] = v;
                }
            }
        }
    }
}

// ---------------------------------------------------------------------------
// Flash attention, bf16 tensor cores. 8 warps, 128 q-rows per block.
// Q/K/P fragments via direct word LDS; V B-fragments via ldmatrix.x4.trans.
// ---------------------------------------------------------------------------
#define QSW 36   // words per row (4 mod 32 -> conflict-free)

__global__ __launch_bounds__(256) void flash_attn_bf16()
{
    __shared__ unsigned QPw[128 * QSW];   // Q then P (per-warp rows)
    __shared__ unsigned Kw[64 * QSW];
    __shared__ unsigned Vw[64 * QSW];     // row stride 144B: ldmatrix conflict-free

    const int bh = blockIdx.y;
    const int q0 = blockIdx.x * 128;
    const __nv_bfloat16* Q = g_q + (size_t)bh * S_ * DH_;
    const __nv_bfloat16* K = g_k + (size_t)bh * S_ * DH_;
    const __nv_bfloat16* V = g_v + (size_t)bh * S_ * DH_;

    const int tid = threadIdx.x;
    const int lane = tid & 31;
    const int wid = tid >> 5;       // 0..7
    const int g = lane >> 2;
    const int t4 = lane & 3;
    const int qr = wid * 16;

    const unsigned vbase = (unsigned)__cvta_generic_to_shared(Vw);

    // load Q tile: 128 rows x 8 uint4
    {
        const uint4* Qg = (const uint4*)(Q + (size_t)q0 * DH_);
        for (int i = tid; i < 1024; i += 256) {
            const int r = i >> 3, c = i & 7;
            *(uint4*)&QPw[r * QSW + c * 4] = Qg[i];
        }
    }
    __syncthreads();

    unsigned qa[4][4];
    #pragma unroll
    for (int kk = 0; kk < 4; kk++) {
        const int r = qr + g;
        qa[kk][0] = QPw[r * QSW + kk * 8 + t4];
        qa[kk][1] = QPw[(r + 8) * QSW + kk * 8 + t4];
        qa[kk][2] = QPw[r * QSW + kk * 8 + t4 + 4];
        qa[kk][3] = QPw[(r + 8) * QSW + kk * 8 + t4 + 4];
    }

    float m_i[2] = {-1e30f, -1e30f};
    float l_i[2] = {0.f, 0.f};
    float oc[8][4];
    #pragma unroll
    for (int n = 0; n < 8; n++)
        #pragma unroll
        for (int c = 0; c < 4; c++) oc[n][c] = 0.f;

    for (int j0 = 0; j0 < S_; j0 += 64) {
        // load K, V tiles: 64 rows x 8 uint4 each
        {
            const uint4* Kg = (const uint4*)(K + (size_t)j0 * DH_);
            const uint4* Vg = (const uint4*)(V + (size_t)j0 * DH_);
            for (int i = tid; i < 512; i += 256) {
                const int r = i >> 3, c = i & 7;
                *(uint4*)&Kw[r * QSW + c * 4] = Kg[i];
                *(uint4*)&Vw[r * QSW + c * 4] = Vg[i];
            }
        }
        __syncthreads();

        // scores = Q . K^T  (16 q rows x 64 keys per warp)
        float sc[8][4];
        #pragma unroll
        for (int nt = 0; nt < 8; nt++)
            #pragma unroll
            for (int c = 0; c < 4; c++) sc[nt][c] = 0.f;
        #pragma unroll
        for (int nt = 0; nt < 8; nt++) {
            const int kr = nt * 8 + g;
            #pragma unroll
            for (int kk = 0; kk < 4; kk++) {
                unsigned bf[2];
                bf[0] = Kw[kr * QSW + kk * 8 + t4];
                bf[1] = Kw[kr * QSW + kk * 8 + t4 + 4];
                mma_bf16(sc[nt], qa[kk], bf);
            }
        }

        // online softmax (rows g and g+8 of this warp's 16)
        #pragma unroll
        for (int h = 0; h < 2; h++) {
            const int i0 = h * 2;
            float mx = -1e30f;
            #pragma unroll
            for (int nt = 0; nt < 8; nt++) {
                sc[nt][i0]     *= 0.125f;
                sc[nt][i0 + 1] *= 0.125f;
                mx = fmaxf(mx, fmaxf(sc[nt][i0], sc[nt][i0 + 1]));
            }
            mx = fmaxf(mx, __shfl_xor_sync(0xffffffffu, mx, 1));
            mx = fmaxf(mx, __shfl_xor_sync(0xffffffffu, mx, 2));
            const float m_new = fmaxf(m_i[h], mx);
            const float alpha = __expf(m_i[h] - m_new);
            m_i[h] = m_new;
            float rs = 0.f;
            const int prow = qr + g + h * 8;
            #pragma unroll
            for (int nt = 0; nt < 8; nt++) {
                const float p0 = __expf(sc[nt][i0] - m_new);
                const float p1 = __expf(sc[nt][i0 + 1] - m_new);
                rs += p0 + p1;
                QPw[prow * QSW + nt * 4 + t4] = pack_bf16(p0, p1);
            }
            rs += __shfl_xor_sync(0xffffffffu, rs, 1);
            rs += __shfl_xor_sync(0xffffffffu, rs, 2);
            l_i[h] = l_i[h] * alpha + rs;
            #pragma unroll
            for (int nt = 0; nt < 8; nt++) {
                oc[nt][i0]     *= alpha;
                oc[nt][i0 + 1] *= alpha;
            }
        }
        __syncwarp();

        // O += P . V  (keys in 4 chunks of 16; V fragments via ldmatrix.trans)
        #pragma unroll
        for (int kk = 0; kk < 4; kk++) {
            unsigned pa[4];
            const int r = qr + g;
            pa[0] = QPw[r * QSW + kk * 8 + t4];
            pa[1] = QPw[(r + 8) * QSW + kk * 8 + t4];
            pa[2] = QPw[r * QSW + kk * 8 + t4 + 4];
            pa[3] = QPw[(r + 8) * QSW + kk * 8 + t4 + 4];
            const int krow = kk * 16 + (lane & 15);
            const int dwh = (lane >> 4) << 2;
            #pragma unroll
            for (int nt2 = 0; nt2 < 4; nt2++) {
                const unsigned addr =
                    vbase + (unsigned)(krow * QSW + nt2 * 8 + dwh) * 4;
                unsigned b0, b1, b2, b3;
                asm volatile(
                    "ldmatrix.sync.aligned.m8n8.x4.trans.shared.b16 "
                    "{%0,%1,%2,%3}, [%4];"
                    : "=r"(b0), "=r"(b1), "=r"(b2), "=r"(b3)
                    : "r"(addr));
                unsigned blo[2] = {b0, b1};
                unsigned bhi[2] = {b2, b3};
                mma_bf16(oc[2 * nt2],     pa, blo);
                mma_bf16(oc[2 * nt2 + 1], pa, bhi);
            }
        }
        __syncthreads();
    }

    // epilogue: ctx (bf16) in [B, S, H] layout
    const int bb = bh >> 4;
    const int nh = bh & 15;
    const float inv0 = 1.0f / l_i[0];
    const float inv1 = 1.0f / l_i[1];
    #pragma unroll
    for (int nt = 0; nt < 8; nt++) {
        const int d = nt * 8 + 2 * t4;
        const int s0 = q0 + qr + g;
        __nv_bfloat162 v0 = __float22bfloat162_rn(
            make_float2(oc[nt][0] * inv0, oc[nt][1] * inv0));
        __nv_bfloat162 v1 = __float22bfloat162_rn(
            make_float2(oc[nt][2] * inv1, oc[nt][3] * inv1));
        *(__nv_bfloat162*)&g_ctx[((size_t)bb * S_ + s0) * H_ + nh * DH_ + d] = v0;
        *(__nv_bfloat162*)&g_ctx[((size_t)bb * S_ + s0 + 8) * H_ + nh * DH_ + d] = v1;
    }
}

// ---------------------------------------------------------------------------
// LayerNorm
// ---------------------------------------------------------------------------
__global__ __launch_bounds__(256) void layernorm(
    const float* __restrict__ gamma, const float* __restrict__ beta,
    float* __restrict__ out)
{
    __shared__ float sh1[8];
    __shared__ float sh2[8];

    const int row = blockIdx.x;
    const int tid = threadIdx.x;
    const float4 v = ((const float4*)(g_h + (size_t)row * H_))[tid];

    float sum = v.x + v.y + v.z + v.w;
    float sq  = v.x * v.x + v.y * v.y + v.z * v.z + v.w * v.w;

    #pragma unroll
    for (int off = 16; off >= 1; off >>= 1) {
        sum += __shfl_xor_sync(0xffffffffu, sum, off);
        sq  += __shfl_xor_sync(0xffffffffu, sq,  off);
    }
    const int wid = tid >> 5;
    if ((tid & 31) == 0) { sh1[wid] = sum; sh2[wid] = sq; }
    __syncthreads();
    if (tid < 8) {
        sum = sh1[tid]; sq = sh2[tid];
        #pragma unroll
        for (int off = 4; off >= 1; off >>= 1) {
            sum += __shfl_xor_sync(0xffu, sum, off);
            sq  += __shfl_xor_sync(0xffu, sq,  off);
        }
        if (tid == 0) { sh1[0] = sum; sh2[0] = sq; }
    }
    __syncthreads();

    const float mean = sh1[0] * (1.0f / H_);
    const float var  = sh2[0] * (1.0f / H_) - mean * mean;
    const float rstd = rsqrtf(var + 1e-12f);

    const float4 gv = ((const float4*)gamma)[tid];
    const float4 bt = ((const float4*)beta)[tid];
    float4 r;
    r.x = (v.x - mean) * rstd * gv.x + bt.x;
    r.y = (v.y - mean) * rstd * gv.y + bt.y;
    r.z = (v.z - mean) * rstd * gv.z + bt.z;
    r.w = (v.w - mean) * rstd * gv.w + bt.w;
    ((float4*)(out + (size_t)row * H_))[tid] = r;
}

// ---------------------------------------------------------------------------
extern "C" void kernel_launch(void* const* d_in, const int* in_sizes, int n_in,
                              void* d_out, int out_size)
{
    const float* X     = (const float*)d_in[0];
    const float* Wq    = (const float*)d_in[1];
    const float* bq    = (const float*)d_in[2];
    const float* Wk    = (const float*)d_in[3];
    const float* bk    = (const float*)d_in[4];
    const float* Wv    = (const float*)d_in[5];
    const float* bv    = (const float*)d_in[6];
    const float* Wo    = (const float*)d_in[7];
    const float* bo    = (const float*)d_in[8];
    const float* gamma = (const float*)d_in[9];
    const float* beta  = (const float*)d_in[10];
    float* out = (float*)d_out;

    __nv_bfloat16 *xb, *wq, *wk, *wv, *wo, *ctxb;
    cudaGetSymbolAddress((void**)&xb,   g_xb);
    cudaGetSymbolAddress((void**)&wq,   g_wq);
    cudaGetSymbolAddress((void**)&wk,   g_wk);
    cudaGetSymbolAddress((void**)&wv,   g_wv);
    cudaGetSymbolAddress((void**)&wo,   g_wo);
    cudaGetSymbolAddress((void**)&ctxb, g_ctx);

    const int gemm_smem = STG * STGW * 2 * (int)sizeof(unsigned);  // 81920
    cudaFuncSetAttribute(gemm_bf16, cudaFuncAttributeMaxDynamicSharedMemorySize,
                         gemm_smem);

    // 0) fp32 -> bf16 conversion of X and weights
    convert_bf16<<<12288, 256>>>(X, Wq, Wk, Wv, Wo);

    // 1) QKV projections
    gemm_bf16<<<dim3(H_ / 128, M_ / 128, 3), 256, gemm_smem>>>(
        xb, wq, wk, wv, bq, bk, bv, nullptr, 0);

    // 2) flash attention
    flash_attn_bf16<<<dim3(S_ / 128, B_ * NH_), 256>>>();

    // 3) output projection + bias + residual
    gemm_bf16<<<dim3(H_ / 128, M_ / 128, 1), 256, gemm_smem>>>(
        ctxb, wo, nullptr, nullptr, bo, nullptr, nullptr, X, 1);

    // 4) layernorm
    layernorm<<<M_, 256>>>(gamma, beta, out);
}